// round 9
// baseline (speedup 1.0000x reference)
#include <cuda_runtime.h>
#include <math.h>

// Problem constants
#define Nn 128
#define Cc 64
#define Tt 128
#define Vv 25
#define Rr 8
#define Hh 12

// Scratch (device globals; zero-initialized, no allocation allowed)
__device__ float g_xm[Nn * Cc * Vv];             // mean over T        (0.8 MB)
__device__ float g_rel[Nn * Rr * Vv * Vv];       // tanh relation      (2.56 MB, L2-resident)
__device__ float g_a[Nn * Vv];                   // SE joint gate      (12.8 KB)
__device__ int   g_cnt[Nn];                      // arrival counters (monotone; use %64)

// ========== Kernel 12: mean over T, then last-block-per-n does SE + rel ==========
// 8192 blocks (one per (n,c)), 200 threads. Phase A = proven k1 body.
// The 64th block to finish for a given n (atomicAdd; old%64==63 keeps it
// deterministic across graph replays without any counter reset) runs phase B:
// SE gate a[n,v], x1/x2, rel[n,r,u,v] = tanh(x1[r,u]-x2[r,v]).
__global__ void __launch_bounds__(200) k12_stats(
        const float* __restrict__ x,
        const float* __restrict__ w1, const float* __restrict__ b1,
        const float* __restrict__ w2, const float* __restrict__ b2,
        const float* __restrict__ sw1, const float* __restrict__ sb1,
        const float* __restrict__ sw2, const float* __restrict__ sb2) {
    const int b = blockIdx.x;                 // n*C + c
    const int n = b >> 6;
    const int j = threadIdx.x;                // 0..199

    // ---- Phase A: xm[b, v] = mean_t x[b, t, v] ----
    // stride 800 floats == 0 mod 25 -> each float4 component keeps a FIXED v.
    const float4* xp4 = reinterpret_cast<const float4*>(x + (size_t)b * (Tt * Vv));
    float4 a0 = xp4[j];
    float4 a1 = xp4[j + 200];
    float4 a2 = xp4[j + 400];
    float4 a3 = xp4[j + 600];

    __shared__ float red[800];
    __shared__ float xm_sh[Cc * Vv];          // phase B
    __shared__ float x1_sh[Rr * Vv], x2_sh[Rr * Vv];
    __shared__ float s_sh[Vv], h_sh[Hh];
    __shared__ int lastFlag;

    red[4 * j + 0] = a0.x + a1.x + a2.x + a3.x;
    red[4 * j + 1] = a0.y + a1.y + a2.y + a3.y;
    red[4 * j + 2] = a0.z + a1.z + a2.z + a3.z;
    red[4 * j + 3] = a0.w + a1.w + a2.w + a3.w;
    __syncthreads();

    if (j < Vv) {
        float tot = 0.f;
        #pragma unroll
        for (int p = 0; p < 32; p++) tot += red[j + Vv * p];
        g_xm[b * Vv + j] = tot * (1.0f / Tt);
        __threadfence();                      // release xm before arrival
    }
    __syncthreads();
    if (j == 0) {
        int old = atomicAdd(&g_cnt[n], 1);
        lastFlag = ((old & 63) == 63) ? 1 : 0;
    }
    __syncthreads();
    if (!lastFlag) return;
    __threadfence();                          // acquire all 64 xm slices

    // ---- Phase B (one block per n) ----
    for (int i = j; i < Cc * Vv; i += 200) xm_sh[i] = g_xm[n * Cc * Vv + i];
    __syncthreads();

    // s[v] = mean_c xm
    if (j < Vv) {
        float acc = 0.f;
        for (int c = 0; c < Cc; c++) acc += xm_sh[c * Vv + j];
        s_sh[j] = acc * (1.0f / Cc);
    }
    __syncthreads();
    if (j < Hh) {
        float acc = __ldg(sb1 + j);
        for (int v = 0; v < Vv; v++) acc += __ldg(sw1 + j * Vv + v) * s_sh[v];
        h_sh[j] = fmaxf(acc, 0.f);
    }
    __syncthreads();
    if (j < Vv) {
        float acc = __ldg(sb2 + j);
        for (int q = 0; q < Hh; q++) acc += __ldg(sw2 + j * Hh + q) * h_sh[q];
        g_a[n * Vv + j] = 1.0f / (1.0f + expf(-acc));
    }

    // x1[r,v], x2[r,v] — 200 threads == Rr*Vv exactly
    {
        int r = j / Vv, v = j % Vv;
        float acc1 = __ldg(b1 + r), acc2 = __ldg(b2 + r);
        for (int c = 0; c < Cc; c++) {
            float xm = xm_sh[c * Vv + v];
            acc1 += __ldg(w1 + r * Cc + c) * xm;
            acc2 += __ldg(w2 + r * Cc + c) * xm;
        }
        x1_sh[j] = acc1;
        x2_sh[j] = acc2;
    }
    __syncthreads();

    // rel[r,u,v] = tanh(x1[r,u] - x2[r,v])
    float* relp = g_rel + (size_t)n * (Rr * Vv * Vv);
    for (int i = j; i < Rr * Vv * Vv; i += 200) {
        int r = i / (Vv * Vv), rem = i % (Vv * Vv);
        int u = rem / Vv, v = rem % Vv;
        relp[i] = tanhf(x1_sh[r * Vv + u] - x2_sh[r * Vv + v]);
    }
}

// ============ Kernel 3: weight reconstruction + GEMM ============
// One block per (n,c), 128 threads, one t-row per thread. launch_bounds
// (128,10) caps regs at 51 so >=10 blocks/SM stay resident (v5's prologue
// had pushed regs past the 46 of the proven v2 body and cost occupancy).
__global__ void __launch_bounds__(128, 10) k3_gemm(const float* __restrict__ x,
                                                   const float* __restrict__ Astat,
                                                   const float* __restrict__ w4,
                                                   const float* __restrict__ b4,
                                                   float* __restrict__ out) {
    __shared__ float xs[Tt * Vv];                      // 12.8 KB; reused as out staging
    __shared__ __align__(16) float Ws[Vv * 28];        // padded rows: 112 B each

    const int b = blockIdx.x;           // n*C + c
    const int n = b >> 6;
    const int c = b & 63;
    const int tid = threadIdx.x;        // 0..127 == t

    // Load x tile (800 float4, coalesced; the only cold-DRAM read)
    const float4* xp4 = reinterpret_cast<const float4*>(x + (size_t)b * (Tt * Vv));
    float4* xs4 = reinterpret_cast<float4*>(xs);
    #pragma unroll
    for (int i = tid; i < (Tt * Vv) / 4; i += 128) xs4[i] = xp4[i];

    // Zero padding columns 25..27 of Ws
    if (tid < Vv * 3) {
        int u = tid / 3, p = tid % 3;
        Ws[u * 28 + 25 + p] = 0.f;
    }

    // Reconstruct weight matrix from rel (all operands L2-resident):
    // Ws[u,v] = (sum_r w4[c,r]*rel[n,r,u,v] + b4[c] + A[u,v]) * a[n,v]
    {
        float w4c[Rr];
        #pragma unroll
        for (int r = 0; r < Rr; r++) w4c[r] = __ldg(w4 + c * Rr + r);
        const float bias = __ldg(b4 + c);
        const float* relp = g_rel + (size_t)n * (Rr * Vv * Vv);
        const float* ap = g_a + n * Vv;
        #pragma unroll 1
        for (int e = tid; e < Vv * Vv; e += 128) {
            int u = e / Vv, v = e % Vv;
            float acc = bias + __ldg(Astat + e);
            #pragma unroll
            for (int r = 0; r < Rr; r++) acc += w4c[r] * relp[r * (Vv * Vv) + e];
            Ws[u * 28 + v] = acc * __ldg(ap + v);
        }
    }
    __syncthreads();

    // Pull this thread's x row into registers (lane stride 25 ⊥ 32: conflict-free)
    float xv[Vv];
    #pragma unroll
    for (int v = 0; v < Vv; v++) xv[v] = xs[tid * Vv + v];
    __syncthreads();   // xs now free for output staging

    #pragma unroll 1
    for (int u = 0; u < Vv; u++) {
        const float4* wr = reinterpret_cast<const float4*>(Ws + u * 28);
        float4 w0 = wr[0], w1 = wr[1], w2 = wr[2], w3 = wr[3];
        float4 w4r = wr[4], w5 = wr[5], w6 = wr[6];
        float acc0, acc1;
        acc0  = w0.x * xv[0];
        acc1  = w0.y * xv[1];
        acc0 += w0.z * xv[2];
        acc1 += w0.w * xv[3];
        acc0 += w1.x * xv[4];
        acc1 += w1.y * xv[5];
        acc0 += w1.z * xv[6];
        acc1 += w1.w * xv[7];
        acc0 += w2.x * xv[8];
        acc1 += w2.y * xv[9];
        acc0 += w2.z * xv[10];
        acc1 += w2.w * xv[11];
        acc0 += w3.x * xv[12];
        acc1 += w3.y * xv[13];
        acc0 += w3.z * xv[14];
        acc1 += w3.w * xv[15];
        acc0 += w4r.x * xv[16];
        acc1 += w4r.y * xv[17];
        acc0 += w4r.z * xv[18];
        acc1 += w4r.w * xv[19];
        acc0 += w5.x * xv[20];
        acc1 += w5.y * xv[21];
        acc0 += w5.z * xv[22];
        acc1 += w5.w * xv[23];
        acc0 += w6.x * xv[24];
        xs[tid * Vv + u] = acc0 + acc1;
    }
    __syncthreads();

    float4* op4 = reinterpret_cast<float4*>(out + (size_t)b * (Tt * Vv));
    #pragma unroll
    for (int i = tid; i < (Tt * Vv) / 4; i += 128) __stcs(op4 + i, xs4[i]);
}

extern "C" void kernel_launch(void* const* d_in, const int* in_sizes, int n_in,
                              void* d_out, int out_size) {
    const float* x   = (const float*)d_in[0];
    const float* A   = (const float*)d_in[1];
    const float* w1  = (const float*)d_in[2];
    const float* b1  = (const float*)d_in[3];
    const float* w2  = (const float*)d_in[4];
    const float* b2  = (const float*)d_in[5];
    const float* w4  = (const float*)d_in[6];
    const float* b4  = (const float*)d_in[7];
    const float* sw1 = (const float*)d_in[8];
    const float* sb1 = (const float*)d_in[9];
    const float* sw2 = (const float*)d_in[10];
    const float* sb2 = (const float*)d_in[11];
    float* out = (float*)d_out;

    k12_stats<<<Nn * Cc, 200>>>(x, w1, b1, w2, b2, sw1, sb1, sw2, sb2);
    k3_gemm<<<Nn * Cc, 128>>>(x, A, w4, b4, out);
}